// round 10
// baseline (speedup 1.0000x reference)
#include <cuda_runtime.h>
#include <cstdint>

#define NN    2000
#define D     16
#define TILE  8192           // B*T*D = 8*64*16
#define BR    3
#define MAXPAD 16384         // >= n3 + 3*NN

typedef unsigned long long ull;

// Scratch (device globals: no allocation allowed in kernel_launch)
__device__ float g_y2[1800 * TILE];   // fc(h2), consumed by gather
__device__ int   g_counts[NN];
__device__ int   g_off[NN];           // padded exclusive offsets (multiples of 4)
__device__ int   g_order[NN];         // nodes sorted by descending count
__device__ int   g_perm[MAXPAD];      // leaf index, ~first for pad slots
__device__ int   g_pad_total;
__device__ __align__(16) int   g_pe[MAXPAD];        // pe3[perm[k]], dense
__device__ __align__(16) float g_scl[MAXPAD * 16];  // scales (0 for pad), dense

// ---- packed f32x2 helpers (gather only) ----
__device__ __forceinline__ void upk2(ull p, float& lo, float& hi) {
    asm("mov.b64 {%0,%1},%2;" : "=f"(lo), "=f"(hi) : "l"(p));
}
__device__ __forceinline__ ull fma2(ull a, ull b, ull c) {
    ull r; asm("fma.rn.f32x2 %0,%1,%2,%3;" : "=l"(r) : "l"(a), "l"(b), "l"(c)); return r;
}

// One block: counts, padded offsets, scatter permutation, pad fill, node ordering.
__global__ void __launch_bounds__(1024) prep_kernel(const int* __restrict__ cn3, int n3) {
    __shared__ int sCnt[2048];
    __shared__ int sScan[2048];
    __shared__ int sPos[2048];
    __shared__ int bCnt[32];
    __shared__ int bCur[32];
    const int t = threadIdx.x;

    sCnt[t] = 0; sCnt[t + 1024] = 0;
    __syncthreads();
    for (int j = t; j < n3; j += 1024) atomicAdd(&sCnt[cn3[j]], 1);
    __syncthreads();

    // exclusive scan of PADDED counts (pad each to multiple of 4)
    sScan[t]        = (t == 0) ? 0 : ((sCnt[t - 1] + 3) & ~3);
    sScan[t + 1024] = (sCnt[t + 1023] + 3) & ~3;
    __syncthreads();
    for (int d = 1; d < 2048; d <<= 1) {
        int a = sScan[t]        + ((t >= d)        ? sScan[t - d]        : 0);
        int b = sScan[t + 1024] + ((t + 1024 >= d) ? sScan[t + 1024 - d] : 0);
        __syncthreads();
        sScan[t] = a; sScan[t + 1024] = b;
        __syncthreads();
    }

    if (t < NN)        { g_counts[t] = sCnt[t];           g_off[t] = sScan[t]; }
    if (t + 1024 < NN) { g_counts[t+1024] = sCnt[t+1024]; g_off[t+1024] = sScan[t+1024]; }
    if (t == 0) g_pad_total = sScan[NN - 1] + ((sCnt[NN - 1] + 3) & ~3);
    if (t < 32) bCnt[t] = 0;
    __syncthreads();

    // node ordering buckets (descending count) — sCnt still holds counts
    for (int i = t; i < NN; i += 1024) atomicAdd(&bCnt[min(sCnt[i], 31)], 1);

    sPos[t] = 0; sPos[t + 1024] = 0;
    __syncthreads();
    if (t == 0) {
        int run = 0;
        for (int c = 31; c >= 0; c--) { bCur[c] = run; run += bCnt[c]; }
    }
    __syncthreads();
    for (int j = t; j < n3; j += 1024) {
        int c = cn3[j];
        int pos = atomicAdd(&sPos[c], 1);
        g_perm[sScan[c] + pos] = j;
    }
    for (int i = t; i < NN; i += 1024) {
        int pos = atomicAdd(&bCur[min(sCnt[i], 31)], 1);
        g_order[pos] = i;
    }
    __syncthreads();

    // pad fill: duplicate first leaf index, flagged with ~ (scale will be 0)
    for (int i = t; i < NN; i += 1024) {
        int c = sCnt[i];
        if (c == 0) continue;
        int off = g_off[i];
        int pc = (c + 3) & ~3;
        int first = g_perm[off];
        for (int k = c; k < pc; k++) g_perm[off + k] = ~first;
    }
}

// Grid-parallel: resolve all gather-side indirection into dense arrays.
__global__ void __launch_bounds__(256) scale_fill_kernel(
    const float* __restrict__ A, const int* __restrict__ pe3,
    const int* __restrict__ pn3, const int* __restrict__ cn3)
{
    int idx = blockIdx.x * blockDim.x + threadIdx.x;     // over pad_total*16
    if (idx >= g_pad_total * 16) return;
    int k = idx >> 4, f = idx & 15;
    int j = g_perm[k];
    bool pad = (j < 0);
    if (pad) j = ~j;
    g_scl[idx] = pad ? 0.f
                     : A[(size_t)f * NN * NN + (size_t)pn3[j] * NN + (size_t)cn3[j]];
    if (f == 0) g_pe[k] = pe3[j];
}

// Copy x -> out for nodes with no leaves (runs on side stream, overlapped with tree).
__global__ void __launch_bounds__(256) copy0_kernel(
    const float* __restrict__ x, float* __restrict__ out)
{
    const int node = blockIdx.x;
    if (g_counts[node] != 0) return;
    const int t = threadIdx.x;
    const float4* src = (const float4*)(x   + (size_t)node * TILE);
    float4*       dst = (float4*)(out + (size_t)node * TILE);
    #pragma unroll
    for (int i = 0; i < 8; i++) {
        float4 v = __ldcs(src + t + i * 256);
        __stcs(dst + t + i * 256, v);
    }
}

// fc over 16 features with 2 threads/row: each thread owns 8 contiguous features
// (part = 0 or 8); partner half fetched via shfl_xor lane^1.
__device__ __forceinline__ void fc8(const float h[8], int part,
                                    const float* __restrict__ sW,
                                    const float* __restrict__ sb, float y[8]) {
    float ho[8];
    #pragma unroll
    for (int d = 0; d < 8; d++) ho[d] = __shfl_xor_sync(0xffffffffu, h[d], 1);
    const int op = part ^ 8;
    #pragma unroll
    for (int f = 0; f < 8; f++) {
        const float* wr = sW + (part + f) * 16;
        float acc = sb[part + f];
        #pragma unroll
        for (int d = 0; d < 8; d++) acc = fmaf(h[d],  wr[part + d], acc);
        #pragma unroll
        for (int d = 0; d < 8; d++) acc = fmaf(ho[d], wr[op + d],   acc);
        y[f] = acc;
    }
}

// Fused levels 0+1: one block per (root, eighth-tile). 128 threads, 2/row.
// __launch_bounds__(128, 6) caps regs at ~85 -> 6 blocks/SM (was 233 regs, 2 blocks).
__global__ void __launch_bounds__(128, 6) tree_kernel(
    const float* __restrict__ x, const float* __restrict__ A,
    const float* __restrict__ W, const float* __restrict__ bias,
    const int* __restrict__ root_ids,
    const int* __restrict__ pn1, const int* __restrict__ cn1,
    const int* __restrict__ pn2, const int* __restrict__ cn2)
{
    __shared__ float sW[256];
    __shared__ float sb16[16];
    __shared__ float sS1[3][16];
    __shared__ float sS2[9][16];
    __shared__ int   sCn1[3];
    __shared__ int   sCn2[9];

    const int rp  = blockIdx.x >> 3;
    const int oct = blockIdx.x & 7;
    const int t   = threadIdx.x;

    sW[t] = W[t];
    sW[t + 128] = W[t + 128];
    if (t < 16) sb16[t] = bias[t];

    // 192 scale entries loaded by 128 threads (two passes)
    #pragma unroll
    for (int pass = 0; pass < 2; pass++) {
        int u = t + pass * 128;
        if (u < 48) {
            int c = u >> 4, f = u & 15;
            int j1 = rp * 3 + c;
            int pnj = pn1[j1], cnj = cn1[j1];
            sS1[c][f] = A[(size_t)f * NN * NN + (size_t)pnj * NN + (size_t)cnj];
            if (f == 0) sCn1[c] = cnj;
        } else if (u < 192) {
            int v = u - 48;
            int c = v >> 4, f = v & 15;
            int j2 = rp * 9 + c;
            int pnj = pn2[j2], cnj = cn2[j2];
            sS2[c][f] = A[(size_t)f * NN * NN + (size_t)pnj * NN + (size_t)cnj];
            if (f == 0) sCn2[c] = cnj;
        }
    }

    const int row  = oct * 64 + (t >> 1);
    const int part = (t & 1) * 8;
    const size_t roff = (size_t)row * D + part;

    float h[8];
    {
        const float4* pr = (const float4*)(x + (size_t)root_ids[rp] * TILE + roff);
        float4 a0 = pr[0], a1 = pr[1];
        h[0]=a0.x; h[1]=a0.y; h[2]=a0.z; h[3]=a0.w;
        h[4]=a1.x; h[5]=a1.y; h[6]=a1.z; h[7]=a1.w;
    }
    __syncthreads();

    float yp[8];
    fc8(h, part, sW, sb16, yp);          // fc(root)

    #pragma unroll
    for (int c1 = 0; c1 < 3; c1++) {
        float h1[8];
        {
            const float4* xr = (const float4*)(x + (size_t)sCn1[c1] * TILE + roff);
            float4 x0 = xr[0], x1 = xr[1];
            h1[0]=fmaf(yp[0],sS1[c1][part+0],x0.x);
            h1[1]=fmaf(yp[1],sS1[c1][part+1],x0.y);
            h1[2]=fmaf(yp[2],sS1[c1][part+2],x0.z);
            h1[3]=fmaf(yp[3],sS1[c1][part+3],x0.w);
            h1[4]=fmaf(yp[4],sS1[c1][part+4],x1.x);
            h1[5]=fmaf(yp[5],sS1[c1][part+5],x1.y);
            h1[6]=fmaf(yp[6],sS1[c1][part+6],x1.z);
            h1[7]=fmaf(yp[7],sS1[c1][part+7],x1.w);
        }
        float y1[8];
        fc8(h1, part, sW, sb16, y1);     // fc(h1) feeds level-2 children

        #pragma unroll
        for (int c2 = 0; c2 < 3; c2++) {
            const int cc = c1 * 3 + c2;
            float h2[8];
            {
                const float4* xr = (const float4*)(x + (size_t)sCn2[cc] * TILE + roff);
                float4 x0 = xr[0], x1 = xr[1];
                h2[0]=fmaf(y1[0],sS2[cc][part+0],x0.x);
                h2[1]=fmaf(y1[1],sS2[cc][part+1],x0.y);
                h2[2]=fmaf(y1[2],sS2[cc][part+2],x0.z);
                h2[3]=fmaf(y1[3],sS2[cc][part+3],x0.w);
                h2[4]=fmaf(y1[4],sS2[cc][part+4],x1.x);
                h2[5]=fmaf(y1[5],sS2[cc][part+5],x1.y);
                h2[6]=fmaf(y1[6],sS2[cc][part+6],x1.z);
                h2[7]=fmaf(y1[7],sS2[cc][part+7],x1.w);
            }
            float y2v[8];
            fc8(h2, part, sW, sb16, y2v); // store fc(h2) for gather

            float4* dst = (float4*)(g_y2 + ((size_t)rp * 9 + cc) * TILE + roff);
            dst[0] = make_float4(y2v[0], y2v[1], y2v[2], y2v[3]);
            dst[1] = make_float4(y2v[4], y2v[5], y2v[6], y2v[7]);
        }
    }
}

// Eighth-tile blocks, 128 threads, 2/row; packed f32x2 inner loop; no smem/sync.
// Heavy nodes first via g_order; cnt==0 nodes handled by copy0_kernel.
__global__ void __launch_bounds__(128) gather_kernel(
    const float* __restrict__ x, float* __restrict__ out)
{
    const int node = g_order[blockIdx.x >> 3];
    const int cnt  = g_counts[node];
    if (cnt == 0) return;                 // copy0_kernel wrote these

    const int oct  = blockIdx.x & 7;
    const int t    = threadIdx.x;
    const int row  = oct * 64 + (t >> 1);
    const int part = (t & 1) * 8;

    const size_t eoff = (size_t)node * TILE + (size_t)row * D + part;
    const float4* xr = (const float4*)(x + eoff);
    float4 o0 = __ldcs(xr);
    float4 o1 = __ldcs(xr + 1);

    ull acc[4];
    acc[0] = acc[1] = acc[2] = acc[3] = 0ull;   // (0.f,0.f) bit pattern

    const int off = g_off[node];          // multiple of 4
    const int pc  = (cnt + 3) & ~3;
    const size_t roff = (size_t)row * D + part;

    for (int k = 0; k < pc; k += 4) {
        const int4 pe4 = *(const int4*)(g_pe + off + k);
        const ulonglong2* p0 = (const ulonglong2*)(g_y2 + (size_t)pe4.x * TILE + roff);
        const ulonglong2* p1 = (const ulonglong2*)(g_y2 + (size_t)pe4.y * TILE + roff);
        const ulonglong2* p2 = (const ulonglong2*)(g_y2 + (size_t)pe4.z * TILE + roff);
        const ulonglong2* p3 = (const ulonglong2*)(g_y2 + (size_t)pe4.w * TILE + roff);
        ulonglong2 a0 = p0[0], a1 = p0[1];
        ulonglong2 b0 = p1[0], b1 = p1[1];
        ulonglong2 c0 = p2[0], c1 = p2[1];
        ulonglong2 d0 = p3[0], d1 = p3[1];

        // Per-leaf scale stride: 16 floats = 64 B = FOUR ulonglong2.
        const ulonglong2* sp = (const ulonglong2*)(g_scl + (size_t)(off + k) * 16 + part);
        ulonglong2 s0 = sp[0],  s0h = sp[1];
        ulonglong2 s1 = sp[4],  s1h = sp[5];
        ulonglong2 s2 = sp[8],  s2h = sp[9];
        ulonglong2 s3 = sp[12], s3h = sp[13];

        acc[0] = fma2(a0.x, s0.x,  acc[0]); acc[1] = fma2(a0.y, s0.y,  acc[1]);
        acc[2] = fma2(a1.x, s0h.x, acc[2]); acc[3] = fma2(a1.y, s0h.y, acc[3]);

        acc[0] = fma2(b0.x, s1.x,  acc[0]); acc[1] = fma2(b0.y, s1.y,  acc[1]);
        acc[2] = fma2(b1.x, s1h.x, acc[2]); acc[3] = fma2(b1.y, s1h.y, acc[3]);

        acc[0] = fma2(c0.x, s2.x,  acc[0]); acc[1] = fma2(c0.y, s2.y,  acc[1]);
        acc[2] = fma2(c1.x, s2h.x, acc[2]); acc[3] = fma2(c1.y, s2h.y, acc[3]);

        acc[0] = fma2(d0.x, s3.x,  acc[0]); acc[1] = fma2(d0.y, s3.y,  acc[1]);
        acc[2] = fma2(d1.x, s3h.x, acc[2]); acc[3] = fma2(d1.y, s3h.y, acc[3]);
    }

    const float inv = 1.0f / (float)cnt;
    float a0l, a0h, a1l, a1h, a2l, a2h, a3l, a3h;
    upk2(acc[0], a0l, a0h); upk2(acc[1], a1l, a1h);
    upk2(acc[2], a2l, a2h); upk2(acc[3], a3l, a3h);
    o0.x = fmaf(a0l, inv, o0.x); o0.y = fmaf(a0h, inv, o0.y);
    o0.z = fmaf(a1l, inv, o0.z); o0.w = fmaf(a1h, inv, o0.w);
    o1.x = fmaf(a2l, inv, o1.x); o1.y = fmaf(a2h, inv, o1.y);
    o1.z = fmaf(a3l, inv, o1.z); o1.w = fmaf(a3h, inv, o1.w);

    float4* dst = (float4*)(out + eoff);
    __stcs(dst,     o0);
    __stcs(dst + 1, o1);
}

extern "C" void kernel_launch(void* const* d_in, const int* in_sizes, int n_in,
                              void* d_out, int out_size) {
    const float* x    = (const float*)d_in[0];
    const float* A    = (const float*)d_in[1];
    const float* W    = (const float*)d_in[2];
    const float* b    = (const float*)d_in[3];
    const int*   root = (const int*)d_in[4];
    const int*   pn1  = (const int*)d_in[6];
    const int*   cn1  = (const int*)d_in[7];
    const int*   pn2  = (const int*)d_in[9];
    const int*   cn2  = (const int*)d_in[10];
    const int*   pe3  = (const int*)d_in[11];
    const int*   pn3  = (const int*)d_in[12];
    const int*   cn3  = (const int*)d_in[13];
    float* out = (float*)d_out;

    const int n1 = in_sizes[5];    // 600
    const int n3 = in_sizes[11];   // 5400
    const int n_roots = n1 / BR;   // 200

    static cudaStream_t s_side = nullptr;
    static cudaEvent_t  ev_fork = nullptr, ev_join = nullptr;
    if (!s_side) {
        cudaStreamCreateWithFlags(&s_side, cudaStreamNonBlocking);
        cudaEventCreateWithFlags(&ev_fork, cudaEventDisableTiming);
        cudaEventCreateWithFlags(&ev_join, cudaEventDisableTiming);
    }

    // prep + cnt==0 copies + scale resolve only feed gather; overlap with tree_kernel.
    cudaEventRecord(ev_fork, 0);
    cudaStreamWaitEvent(s_side, ev_fork, 0);
    prep_kernel<<<1, 1024, 0, s_side>>>(cn3, n3);
    copy0_kernel<<<NN, 256, 0, s_side>>>(x, out);
    const int padmax = n3 + 3 * NN;
    scale_fill_kernel<<<(padmax * 16 + 255) / 256, 256, 0, s_side>>>(A, pe3, pn3, cn3);
    cudaEventRecord(ev_join, s_side);

    tree_kernel<<<8 * n_roots, 128>>>(x, A, W, b, root, pn1, cn1, pn2, cn2);

    cudaStreamWaitEvent(0, ev_join, 0);
    gather_kernel<<<8 * NN, 128>>>(x, out);
}

// round 11
// speedup vs baseline: 1.9648x; 1.9648x over previous
#include <cuda_runtime.h>
#include <cstdint>

#define NN    2000
#define D     16
#define TILE  8192           // B*T*D = 8*64*16
#define BR    3
#define MAXPAD 16384         // >= n3 + 3*NN

typedef unsigned long long ull;

// Scratch (device globals: no allocation allowed in kernel_launch)
__device__ float g_y2[1800 * TILE];   // fc(h2), consumed by gather
__device__ int   g_counts[NN];
__device__ int   g_off[NN];           // padded exclusive offsets (multiples of 4)
__device__ int   g_order[NN];         // nodes sorted by descending count
__device__ int   g_perm[MAXPAD];      // leaf index, ~first for pad slots
__device__ int   g_pad_total;
__device__ __align__(16) int   g_pe[MAXPAD];        // pe3[perm[k]], dense
__device__ __align__(16) float g_scl[MAXPAD * 16];  // scales (0 for pad), dense

// ---- packed f32x2 helpers (gather only) ----
__device__ __forceinline__ void upk2(ull p, float& lo, float& hi) {
    asm("mov.b64 {%0,%1},%2;" : "=f"(lo), "=f"(hi) : "l"(p));
}
__device__ __forceinline__ ull fma2(ull a, ull b, ull c) {
    ull r; asm("fma.rn.f32x2 %0,%1,%2,%3;" : "=l"(r) : "l"(a), "l"(b), "l"(c)); return r;
}

// One block: counts, padded offsets, scatter permutation, pad fill, node ordering.
__global__ void __launch_bounds__(1024) prep_kernel(const int* __restrict__ cn3, int n3) {
    __shared__ int sCnt[2048];
    __shared__ int sScan[2048];
    __shared__ int sPos[2048];
    __shared__ int bCnt[32];
    __shared__ int bCur[32];
    const int t = threadIdx.x;

    sCnt[t] = 0; sCnt[t + 1024] = 0;
    __syncthreads();
    for (int j = t; j < n3; j += 1024) atomicAdd(&sCnt[cn3[j]], 1);
    __syncthreads();

    // exclusive scan of PADDED counts (pad each to multiple of 4)
    sScan[t]        = (t == 0) ? 0 : ((sCnt[t - 1] + 3) & ~3);
    sScan[t + 1024] = (sCnt[t + 1023] + 3) & ~3;
    __syncthreads();
    for (int d = 1; d < 2048; d <<= 1) {
        int a = sScan[t]        + ((t >= d)        ? sScan[t - d]        : 0);
        int b = sScan[t + 1024] + ((t + 1024 >= d) ? sScan[t + 1024 - d] : 0);
        __syncthreads();
        sScan[t] = a; sScan[t + 1024] = b;
        __syncthreads();
    }

    if (t < NN)        { g_counts[t] = sCnt[t];           g_off[t] = sScan[t]; }
    if (t + 1024 < NN) { g_counts[t+1024] = sCnt[t+1024]; g_off[t+1024] = sScan[t+1024]; }
    if (t == 0) g_pad_total = sScan[NN - 1] + ((sCnt[NN - 1] + 3) & ~3);
    if (t < 32) bCnt[t] = 0;
    __syncthreads();

    // node ordering buckets (descending count) — sCnt still holds counts
    for (int i = t; i < NN; i += 1024) atomicAdd(&bCnt[min(sCnt[i], 31)], 1);

    sPos[t] = 0; sPos[t + 1024] = 0;
    __syncthreads();
    if (t == 0) {
        int run = 0;
        for (int c = 31; c >= 0; c--) { bCur[c] = run; run += bCnt[c]; }
    }
    __syncthreads();
    for (int j = t; j < n3; j += 1024) {
        int c = cn3[j];
        int pos = atomicAdd(&sPos[c], 1);
        g_perm[sScan[c] + pos] = j;
    }
    for (int i = t; i < NN; i += 1024) {
        int pos = atomicAdd(&bCur[min(sCnt[i], 31)], 1);
        g_order[pos] = i;
    }
    __syncthreads();

    // pad fill: duplicate first leaf index, flagged with ~ (scale will be 0)
    for (int i = t; i < NN; i += 1024) {
        int c = sCnt[i];
        if (c == 0) continue;
        int off = g_off[i];
        int pc = (c + 3) & ~3;
        int first = g_perm[off];
        for (int k = c; k < pc; k++) g_perm[off + k] = ~first;
    }
}

// Grid-parallel: resolve all gather-side indirection into dense arrays.
__global__ void __launch_bounds__(256) scale_fill_kernel(
    const float* __restrict__ A, const int* __restrict__ pe3,
    const int* __restrict__ pn3, const int* __restrict__ cn3)
{
    int idx = blockIdx.x * blockDim.x + threadIdx.x;     // over pad_total*16
    if (idx >= g_pad_total * 16) return;
    int k = idx >> 4, f = idx & 15;
    int j = g_perm[k];
    bool pad = (j < 0);
    if (pad) j = ~j;
    g_scl[idx] = pad ? 0.f
                     : A[(size_t)f * NN * NN + (size_t)pn3[j] * NN + (size_t)cn3[j]];
    if (f == 0) g_pe[k] = pe3[j];
}

// Copy x -> out for nodes with no leaves (runs on side stream, overlapped with tree).
__global__ void __launch_bounds__(256) copy0_kernel(
    const float* __restrict__ x, float* __restrict__ out)
{
    const int node = blockIdx.x;
    if (g_counts[node] != 0) return;
    const int t = threadIdx.x;
    const float4* src = (const float4*)(x   + (size_t)node * TILE);
    float4*       dst = (float4*)(out + (size_t)node * TILE);
    #pragma unroll
    for (int i = 0; i < 8; i++) {
        float4 v = __ldcs(src + t + i * 256);
        __stcs(dst + t + i * 256, v);
    }
}

// fc over 16 features with 2 threads/row: each thread owns 8 contiguous features
// (part = 0 or 8); partner half fetched via shfl_xor lane^1.
__device__ __forceinline__ void fc8(const float h[8], int part,
                                    const float* __restrict__ sW,
                                    const float* __restrict__ sb, float y[8]) {
    float ho[8];
    #pragma unroll
    for (int d = 0; d < 8; d++) ho[d] = __shfl_xor_sync(0xffffffffu, h[d], 1);
    const int op = part ^ 8;
    #pragma unroll
    for (int f = 0; f < 8; f++) {
        const float* wr = sW + (part + f) * 16;
        float acc = sb[part + f];
        #pragma unroll
        for (int d = 0; d < 8; d++) acc = fmaf(h[d],  wr[part + d], acc);
        #pragma unroll
        for (int d = 0; d < 8; d++) acc = fmaf(ho[d], wr[op + d],   acc);
        y[f] = acc;
    }
}

// Fused levels 0+1: one block per (root, eighth-tile). 128 threads, 2/row.
// c1/c2 loops NOT unrolled: shrinks the live register set structurally
// (R9's full unroll kept all 9 grandchild chains live -> 233 regs, occ 11.5%;
//  R10's launch_bounds cap spilled catastrophically -> never cap, restructure).
__global__ void __launch_bounds__(128) tree_kernel(
    const float* __restrict__ x, const float* __restrict__ A,
    const float* __restrict__ W, const float* __restrict__ bias,
    const int* __restrict__ root_ids,
    const int* __restrict__ pn1, const int* __restrict__ cn1,
    const int* __restrict__ pn2, const int* __restrict__ cn2)
{
    __shared__ float sW[256];
    __shared__ float sb16[16];
    __shared__ float sS1[3][16];
    __shared__ float sS2[9][16];
    __shared__ int   sCn1[3];
    __shared__ int   sCn2[9];

    const int rp  = blockIdx.x >> 3;
    const int oct = blockIdx.x & 7;
    const int t   = threadIdx.x;

    sW[t] = W[t];
    sW[t + 128] = W[t + 128];
    if (t < 16) sb16[t] = bias[t];

    // 192 scale entries loaded by 128 threads (two passes)
    #pragma unroll
    for (int pass = 0; pass < 2; pass++) {
        int u = t + pass * 128;
        if (u < 48) {
            int c = u >> 4, f = u & 15;
            int j1 = rp * 3 + c;
            int pnj = pn1[j1], cnj = cn1[j1];
            sS1[c][f] = A[(size_t)f * NN * NN + (size_t)pnj * NN + (size_t)cnj];
            if (f == 0) sCn1[c] = cnj;
        } else if (u < 192) {
            int v = u - 48;
            int c = v >> 4, f = v & 15;
            int j2 = rp * 9 + c;
            int pnj = pn2[j2], cnj = cn2[j2];
            sS2[c][f] = A[(size_t)f * NN * NN + (size_t)pnj * NN + (size_t)cnj];
            if (f == 0) sCn2[c] = cnj;
        }
    }

    const int row  = oct * 64 + (t >> 1);
    const int part = (t & 1) * 8;
    const size_t roff = (size_t)row * D + part;

    float h[8];
    {
        const float4* pr = (const float4*)(x + (size_t)root_ids[rp] * TILE + roff);
        float4 a0 = pr[0], a1 = pr[1];
        h[0]=a0.x; h[1]=a0.y; h[2]=a0.z; h[3]=a0.w;
        h[4]=a1.x; h[5]=a1.y; h[6]=a1.z; h[7]=a1.w;
    }
    __syncthreads();

    float yp[8];
    fc8(h, part, sW, sb16, yp);          // fc(root)

    #pragma unroll 1
    for (int c1 = 0; c1 < 3; c1++) {
        float h1[8];
        {
            const float4* xr = (const float4*)(x + (size_t)sCn1[c1] * TILE + roff);
            float4 x0 = xr[0], x1 = xr[1];
            const float* s1v = &sS1[c1][part];
            h1[0]=fmaf(yp[0],s1v[0],x0.x);
            h1[1]=fmaf(yp[1],s1v[1],x0.y);
            h1[2]=fmaf(yp[2],s1v[2],x0.z);
            h1[3]=fmaf(yp[3],s1v[3],x0.w);
            h1[4]=fmaf(yp[4],s1v[4],x1.x);
            h1[5]=fmaf(yp[5],s1v[5],x1.y);
            h1[6]=fmaf(yp[6],s1v[6],x1.z);
            h1[7]=fmaf(yp[7],s1v[7],x1.w);
        }
        float y1[8];
        fc8(h1, part, sW, sb16, y1);     // fc(h1) feeds level-2 children

        #pragma unroll 1
        for (int c2 = 0; c2 < 3; c2++) {
            const int cc = c1 * 3 + c2;
            float h2[8];
            {
                const float4* xr = (const float4*)(x + (size_t)sCn2[cc] * TILE + roff);
                float4 x0 = xr[0], x1 = xr[1];
                const float* s2v = &sS2[cc][part];
                h2[0]=fmaf(y1[0],s2v[0],x0.x);
                h2[1]=fmaf(y1[1],s2v[1],x0.y);
                h2[2]=fmaf(y1[2],s2v[2],x0.z);
                h2[3]=fmaf(y1[3],s2v[3],x0.w);
                h2[4]=fmaf(y1[4],s2v[4],x1.x);
                h2[5]=fmaf(y1[5],s2v[5],x1.y);
                h2[6]=fmaf(y1[6],s2v[6],x1.z);
                h2[7]=fmaf(y1[7],s2v[7],x1.w);
            }
            float y2v[8];
            fc8(h2, part, sW, sb16, y2v); // store fc(h2) for gather

            float4* dst = (float4*)(g_y2 + ((size_t)rp * 9 + cc) * TILE + roff);
            dst[0] = make_float4(y2v[0], y2v[1], y2v[2], y2v[3]);
            dst[1] = make_float4(y2v[4], y2v[5], y2v[6], y2v[7]);
        }
    }
}

// Eighth-tile blocks, 128 threads, 2/row; packed f32x2 inner loop; no smem/sync.
// Heavy nodes first via g_order; cnt==0 nodes handled by copy0_kernel.
__global__ void __launch_bounds__(128) gather_kernel(
    const float* __restrict__ x, float* __restrict__ out)
{
    const int node = g_order[blockIdx.x >> 3];
    const int cnt  = g_counts[node];
    if (cnt == 0) return;                 // copy0_kernel wrote these

    const int oct  = blockIdx.x & 7;
    const int t    = threadIdx.x;
    const int row  = oct * 64 + (t >> 1);
    const int part = (t & 1) * 8;

    const size_t eoff = (size_t)node * TILE + (size_t)row * D + part;
    const float4* xr = (const float4*)(x + eoff);
    float4 o0 = __ldcs(xr);
    float4 o1 = __ldcs(xr + 1);

    ull acc[4];
    acc[0] = acc[1] = acc[2] = acc[3] = 0ull;   // (0.f,0.f) bit pattern

    const int off = g_off[node];          // multiple of 4
    const int pc  = (cnt + 3) & ~3;
    const size_t roff = (size_t)row * D + part;

    for (int k = 0; k < pc; k += 4) {
        const int4 pe4 = *(const int4*)(g_pe + off + k);
        const ulonglong2* p0 = (const ulonglong2*)(g_y2 + (size_t)pe4.x * TILE + roff);
        const ulonglong2* p1 = (const ulonglong2*)(g_y2 + (size_t)pe4.y * TILE + roff);
        const ulonglong2* p2 = (const ulonglong2*)(g_y2 + (size_t)pe4.z * TILE + roff);
        const ulonglong2* p3 = (const ulonglong2*)(g_y2 + (size_t)pe4.w * TILE + roff);
        ulonglong2 a0 = p0[0], a1 = p0[1];
        ulonglong2 b0 = p1[0], b1 = p1[1];
        ulonglong2 c0 = p2[0], c1 = p2[1];
        ulonglong2 d0 = p3[0], d1 = p3[1];

        // Per-leaf scale stride: 16 floats = 64 B = FOUR ulonglong2.
        const ulonglong2* sp = (const ulonglong2*)(g_scl + (size_t)(off + k) * 16 + part);
        ulonglong2 s0 = sp[0],  s0h = sp[1];
        ulonglong2 s1 = sp[4],  s1h = sp[5];
        ulonglong2 s2 = sp[8],  s2h = sp[9];
        ulonglong2 s3 = sp[12], s3h = sp[13];

        acc[0] = fma2(a0.x, s0.x,  acc[0]); acc[1] = fma2(a0.y, s0.y,  acc[1]);
        acc[2] = fma2(a1.x, s0h.x, acc[2]); acc[3] = fma2(a1.y, s0h.y, acc[3]);

        acc[0] = fma2(b0.x, s1.x,  acc[0]); acc[1] = fma2(b0.y, s1.y,  acc[1]);
        acc[2] = fma2(b1.x, s1h.x, acc[2]); acc[3] = fma2(b1.y, s1h.y, acc[3]);

        acc[0] = fma2(c0.x, s2.x,  acc[0]); acc[1] = fma2(c0.y, s2.y,  acc[1]);
        acc[2] = fma2(c1.x, s2h.x, acc[2]); acc[3] = fma2(c1.y, s2h.y, acc[3]);

        acc[0] = fma2(d0.x, s3.x,  acc[0]); acc[1] = fma2(d0.y, s3.y,  acc[1]);
        acc[2] = fma2(d1.x, s3h.x, acc[2]); acc[3] = fma2(d1.y, s3h.y, acc[3]);
    }

    const float inv = 1.0f / (float)cnt;
    float a0l, a0h, a1l, a1h, a2l, a2h, a3l, a3h;
    upk2(acc[0], a0l, a0h); upk2(acc[1], a1l, a1h);
    upk2(acc[2], a2l, a2h); upk2(acc[3], a3l, a3h);
    o0.x = fmaf(a0l, inv, o0.x); o0.y = fmaf(a0h, inv, o0.y);
    o0.z = fmaf(a1l, inv, o0.z); o0.w = fmaf(a1h, inv, o0.w);
    o1.x = fmaf(a2l, inv, o1.x); o1.y = fmaf(a2h, inv, o1.y);
    o1.z = fmaf(a3l, inv, o1.z); o1.w = fmaf(a3h, inv, o1.w);

    float4* dst = (float4*)(out + eoff);
    __stcs(dst,     o0);
    __stcs(dst + 1, o1);
}

extern "C" void kernel_launch(void* const* d_in, const int* in_sizes, int n_in,
                              void* d_out, int out_size) {
    const float* x    = (const float*)d_in[0];
    const float* A    = (const float*)d_in[1];
    const float* W    = (const float*)d_in[2];
    const float* b    = (const float*)d_in[3];
    const int*   root = (const int*)d_in[4];
    const int*   pn1  = (const int*)d_in[6];
    const int*   cn1  = (const int*)d_in[7];
    const int*   pn2  = (const int*)d_in[9];
    const int*   cn2  = (const int*)d_in[10];
    const int*   pe3  = (const int*)d_in[11];
    const int*   pn3  = (const int*)d_in[12];
    const int*   cn3  = (const int*)d_in[13];
    float* out = (float*)d_out;

    const int n1 = in_sizes[5];    // 600
    const int n3 = in_sizes[11];   // 5400
    const int n_roots = n1 / BR;   // 200

    static cudaStream_t s_side = nullptr;
    static cudaEvent_t  ev_fork = nullptr, ev_join = nullptr;
    if (!s_side) {
        cudaStreamCreateWithFlags(&s_side, cudaStreamNonBlocking);
        cudaEventCreateWithFlags(&ev_fork, cudaEventDisableTiming);
        cudaEventCreateWithFlags(&ev_join, cudaEventDisableTiming);
    }

    // prep + cnt==0 copies + scale resolve only feed gather; overlap with tree_kernel.
    cudaEventRecord(ev_fork, 0);
    cudaStreamWaitEvent(s_side, ev_fork, 0);
    prep_kernel<<<1, 1024, 0, s_side>>>(cn3, n3);
    copy0_kernel<<<NN, 256, 0, s_side>>>(x, out);
    const int padmax = n3 + 3 * NN;
    scale_fill_kernel<<<(padmax * 16 + 255) / 256, 256, 0, s_side>>>(A, pe3, pn3, cn3);
    cudaEventRecord(ev_join, s_side);

    tree_kernel<<<8 * n_roots, 128>>>(x, A, W, b, root, pn1, cn1, pn2, cn2);

    cudaStreamWaitEvent(0, ev_join, 0);
    gather_kernel<<<8 * NN, 128>>>(x, out);
}

// round 12
// speedup vs baseline: 2.4313x; 1.2374x over previous
#include <cuda_runtime.h>
#include <cstdint>

#define NN    2000
#define D     16
#define TILE  8192           // B*T*D = 8*64*16
#define BR    3
#define MAXPAD 16384         // >= n3 + 3*NN

// Scratch (device globals: no allocation allowed in kernel_launch)
__device__ float g_y2[1800 * TILE];   // fc(h2), consumed by gather
__device__ int   g_counts[NN];
__device__ int   g_off[NN];           // padded exclusive offsets (multiples of 4)
__device__ int   g_perm[MAXPAD];      // leaf index, ~first for pad slots
__device__ int   g_pad_total;
__device__ __align__(16) int   g_pe[MAXPAD];        // pe3[perm[k]], dense
__device__ __align__(16) float g_scl[MAXPAD * 16];  // scales (0 for pad), dense

// One block: counts, padded exclusive-scan offsets, scatter permutation, pad fill.
__global__ void __launch_bounds__(1024) prep_kernel(const int* __restrict__ cn3, int n3) {
    __shared__ int sCnt[2048];
    __shared__ int sScan[2048];
    const int t = threadIdx.x;

    sCnt[t] = 0; sCnt[t + 1024] = 0;
    __syncthreads();
    for (int j = t; j < n3; j += 1024) atomicAdd(&sCnt[cn3[j]], 1);
    __syncthreads();

    // exclusive scan of PADDED counts (pad each to multiple of 4)
    sScan[t]        = (t == 0) ? 0 : ((sCnt[t - 1] + 3) & ~3);
    sScan[t + 1024] = (sCnt[t + 1023] + 3) & ~3;
    __syncthreads();
    for (int d = 1; d < 2048; d <<= 1) {
        int a = sScan[t]        + ((t >= d)        ? sScan[t - d]        : 0);
        int b = sScan[t + 1024] + ((t + 1024 >= d) ? sScan[t + 1024 - d] : 0);
        __syncthreads();
        sScan[t] = a; sScan[t + 1024] = b;
        __syncthreads();
    }

    if (t < NN)        { g_counts[t] = sCnt[t];           g_off[t] = sScan[t]; }
    if (t + 1024 < NN) { g_counts[t+1024] = sCnt[t+1024]; g_off[t+1024] = sScan[t+1024]; }
    if (t == 0) g_pad_total = sScan[NN - 1] + ((sCnt[NN - 1] + 3) & ~3);

    sCnt[t] = 0; sCnt[t + 1024] = 0;
    __syncthreads();
    for (int j = t; j < n3; j += 1024) {
        int c = cn3[j];
        int pos = atomicAdd(&sCnt[c], 1);
        g_perm[sScan[c] + pos] = j;
    }
    __syncthreads();

    // pad fill: duplicate first leaf index, flagged with ~ (scale will be 0)
    for (int i = t; i < NN; i += 1024) {
        int c = g_counts[i];
        if (c == 0) continue;
        int off = g_off[i];
        int pc = (c + 3) & ~3;
        int first = g_perm[off];
        for (int k = c; k < pc; k++) g_perm[off + k] = ~first;
    }
}

// Grid-parallel: resolve all gather-side indirection into dense arrays.
__global__ void __launch_bounds__(256) scale_fill_kernel(
    const float* __restrict__ A, const int* __restrict__ pe3,
    const int* __restrict__ pn3, const int* __restrict__ cn3)
{
    int idx = blockIdx.x * blockDim.x + threadIdx.x;     // over pad_total*16
    if (idx >= g_pad_total * 16) return;
    int k = idx >> 4, f = idx & 15;
    int j = g_perm[k];
    bool pad = (j < 0);
    if (pad) j = ~j;
    g_scl[idx] = pad ? 0.f
                     : A[(size_t)f * NN * NN + (size_t)pn3[j] * NN + (size_t)cn3[j]];
    if (f == 0) g_pe[k] = pe3[j];
}

// fc over 16 features with 4 threads/row: each thread owns 4 contiguous features
// (part = lane&3). Full 16-vector gathered via 3-shfl butterfly within the 4-lane group.
__device__ __forceinline__ void fc4(const float h[4], int part,
                                    const float* __restrict__ sW,
                                    const float* __restrict__ sb, float y[4]) {
    float g1[4], g2[4], g3[4];
    #pragma unroll
    for (int i = 0; i < 4; i++) g1[i] = __shfl_xor_sync(0xffffffffu, h[i], 1);
    #pragma unroll
    for (int i = 0; i < 4; i++) g2[i] = __shfl_xor_sync(0xffffffffu, h[i], 2);
    #pragma unroll
    for (int i = 0; i < 4; i++) g3[i] = __shfl_xor_sync(0xffffffffu, g1[i], 2);
    const int p0 = part * 4;
    const int p1 = (part ^ 1) * 4;
    const int p2 = (part ^ 2) * 4;
    const int p3 = (part ^ 3) * 4;
    #pragma unroll
    for (int f = 0; f < 4; f++) {
        const float* wr = sW + (p0 + f) * 16;
        float acc = sb[p0 + f];
        #pragma unroll
        for (int i = 0; i < 4; i++) acc = fmaf(h[i],  wr[p0 + i], acc);
        #pragma unroll
        for (int i = 0; i < 4; i++) acc = fmaf(g1[i], wr[p1 + i], acc);
        #pragma unroll
        for (int i = 0; i < 4; i++) acc = fmaf(g2[i], wr[p2 + i], acc);
        #pragma unroll
        for (int i = 0; i < 4; i++) acc = fmaf(g3[i], wr[p3 + i], acc);
        y[f] = acc;
    }
}

// Fused levels 0+1: one block per (root, eighth-tile). 256 threads, 4/row (64 rows).
// 4-wide per-thread state keeps registers low -> 3+ blocks/SM (vs 2 at 2/row).
__global__ void __launch_bounds__(256) tree_kernel(
    const float* __restrict__ x, const float* __restrict__ A,
    const float* __restrict__ W, const float* __restrict__ bias,
    const int* __restrict__ root_ids,
    const int* __restrict__ pn1, const int* __restrict__ cn1,
    const int* __restrict__ pn2, const int* __restrict__ cn2)
{
    __shared__ float sW[256];
    __shared__ float sb16[16];
    __shared__ float sS1[3][16];
    __shared__ float sS2[9][16];
    __shared__ int   sCn1[3];
    __shared__ int   sCn2[9];

    const int rp  = blockIdx.x >> 3;
    const int oct = blockIdx.x & 7;
    const int t   = threadIdx.x;

    sW[t] = W[t];
    if (t < 16) sb16[t] = bias[t];
    if (t >= 32 && t < 32 + 48) {            // distinct warps for S1/S2 loads
        int u = t - 32;
        int c = u >> 4, f = u & 15;
        int j1 = rp * 3 + c;
        int pnj = pn1[j1], cnj = cn1[j1];
        sS1[c][f] = A[(size_t)f * NN * NN + (size_t)pnj * NN + (size_t)cnj];
        if (f == 0) sCn1[c] = cnj;
    } else if (t >= 96 && t < 96 + 144) {
        int u = t - 96;
        int c = u >> 4, f = u & 15;
        int j2 = rp * 9 + c;
        int pnj = pn2[j2], cnj = cn2[j2];
        sS2[c][f] = A[(size_t)f * NN * NN + (size_t)pnj * NN + (size_t)cnj];
        if (f == 0) sCn2[c] = cnj;
    }

    const int part = t & 3;
    const int row  = oct * 64 + (t >> 2);
    const size_t roff = (size_t)row * D + part * 4;
    const int fb = part * 4;

    float h[4];
    {
        float4 v = *(const float4*)(x + (size_t)root_ids[rp] * TILE + roff);
        h[0]=v.x; h[1]=v.y; h[2]=v.z; h[3]=v.w;
    }
    __syncthreads();

    float yp[4];
    fc4(h, part, sW, sb16, yp);          // fc(root)

    #pragma unroll 1
    for (int c1 = 0; c1 < 3; c1++) {
        float h1[4];
        {
            float4 v = *(const float4*)(x + (size_t)sCn1[c1] * TILE + roff);
            const float* s1v = &sS1[c1][fb];
            h1[0]=fmaf(yp[0],s1v[0],v.x);
            h1[1]=fmaf(yp[1],s1v[1],v.y);
            h1[2]=fmaf(yp[2],s1v[2],v.z);
            h1[3]=fmaf(yp[3],s1v[3],v.w);
        }
        float y1[4];
        fc4(h1, part, sW, sb16, y1);     // fc(h1) feeds level-2 children

        #pragma unroll
        for (int c2 = 0; c2 < 3; c2++) {
            const int cc = c1 * 3 + c2;
            float h2[4];
            {
                float4 v = *(const float4*)(x + (size_t)sCn2[cc] * TILE + roff);
                const float* s2v = &sS2[cc][fb];
                h2[0]=fmaf(y1[0],s2v[0],v.x);
                h2[1]=fmaf(y1[1],s2v[1],v.y);
                h2[2]=fmaf(y1[2],s2v[2],v.z);
                h2[3]=fmaf(y1[3],s2v[3],v.w);
            }
            float y2v[4];
            fc4(h2, part, sW, sb16, y2v); // store fc(h2) for gather

            *(float4*)(g_y2 + ((size_t)rp * 9 + cc) * TILE + roff) =
                make_float4(y2v[0], y2v[1], y2v[2], y2v[3]);
        }
    }
}

// Eighth-tile blocks, 128 threads, 2/row. Direct node indexing (R6-measured config).
// Padded 4-wide leaf loop; dense scales; no smem/sync; streaming hints.
__global__ void __launch_bounds__(128) gather_kernel(
    const float* __restrict__ x, float* __restrict__ out)
{
    const int node = blockIdx.x >> 3;
    const int oct  = blockIdx.x & 7;
    const int t    = threadIdx.x;
    const int row  = oct * 64 + (t >> 1);
    const int part = (t & 1) * 8;

    const int cnt = g_counts[node];
    const size_t eoff = (size_t)node * TILE + (size_t)row * D + part;
    const float4* xr = (const float4*)(x + eoff);
    float4 o0 = __ldcs(xr);       // x tile: single use, evict-first
    float4 o1 = __ldcs(xr + 1);

    if (cnt > 0) {
        float acc[8];
        #pragma unroll
        for (int f = 0; f < 8; f++) acc[f] = 0.f;
        const int off = g_off[node];          // multiple of 4
        const int pc  = (cnt + 3) & ~3;
        const size_t roff = (size_t)row * D + part;

        for (int k = 0; k < pc; k += 4) {
            const int4 pe4 = *(const int4*)(g_pe + off + k);
            const float4* p0 = (const float4*)(g_y2 + (size_t)pe4.x * TILE + roff);
            const float4* p1 = (const float4*)(g_y2 + (size_t)pe4.y * TILE + roff);
            const float4* p2 = (const float4*)(g_y2 + (size_t)pe4.z * TILE + roff);
            const float4* p3 = (const float4*)(g_y2 + (size_t)pe4.w * TILE + roff);
            float4 a0 = p0[0], a1 = p0[1];
            float4 b0 = p1[0], b1 = p1[1];
            float4 c0 = p2[0], c1 = p2[1];
            float4 d0 = p3[0], d1 = p3[1];

            const float4* sp = (const float4*)(g_scl + (size_t)(off + k) * 16 + part);
            // leaf i scales at sp + i*4 (16 floats per leaf = 4 float4)
            float4 s0a = sp[0],  s0b = sp[1];
            float4 s1a = sp[4],  s1b = sp[5];
            float4 s2a = sp[8],  s2b = sp[9];
            float4 s3a = sp[12], s3b = sp[13];

            acc[0]=fmaf(a0.x,s0a.x,acc[0]); acc[1]=fmaf(a0.y,s0a.y,acc[1]);
            acc[2]=fmaf(a0.z,s0a.z,acc[2]); acc[3]=fmaf(a0.w,s0a.w,acc[3]);
            acc[4]=fmaf(a1.x,s0b.x,acc[4]); acc[5]=fmaf(a1.y,s0b.y,acc[5]);
            acc[6]=fmaf(a1.z,s0b.z,acc[6]); acc[7]=fmaf(a1.w,s0b.w,acc[7]);

            acc[0]=fmaf(b0.x,s1a.x,acc[0]); acc[1]=fmaf(b0.y,s1a.y,acc[1]);
            acc[2]=fmaf(b0.z,s1a.z,acc[2]); acc[3]=fmaf(b0.w,s1a.w,acc[3]);
            acc[4]=fmaf(b1.x,s1b.x,acc[4]); acc[5]=fmaf(b1.y,s1b.y,acc[5]);
            acc[6]=fmaf(b1.z,s1b.z,acc[6]); acc[7]=fmaf(b1.w,s1b.w,acc[7]);

            acc[0]=fmaf(c0.x,s2a.x,acc[0]); acc[1]=fmaf(c0.y,s2a.y,acc[1]);
            acc[2]=fmaf(c0.z,s2a.z,acc[2]); acc[3]=fmaf(c0.w,s2a.w,acc[3]);
            acc[4]=fmaf(c1.x,s2b.x,acc[4]); acc[5]=fmaf(c1.y,s2b.y,acc[5]);
            acc[6]=fmaf(c1.z,s2b.z,acc[6]); acc[7]=fmaf(c1.w,s2b.w,acc[7]);

            acc[0]=fmaf(d0.x,s3a.x,acc[0]); acc[1]=fmaf(d0.y,s3a.y,acc[1]);
            acc[2]=fmaf(d0.z,s3a.z,acc[2]); acc[3]=fmaf(d0.w,s3a.w,acc[3]);
            acc[4]=fmaf(d1.x,s3b.x,acc[4]); acc[5]=fmaf(d1.y,s3b.y,acc[5]);
            acc[6]=fmaf(d1.z,s3b.z,acc[6]); acc[7]=fmaf(d1.w,s3b.w,acc[7]);
        }
        const float inv = 1.0f / (float)cnt;
        o0.x += acc[0]*inv; o0.y += acc[1]*inv; o0.z += acc[2]*inv; o0.w += acc[3]*inv;
        o1.x += acc[4]*inv; o1.y += acc[5]*inv; o1.z += acc[6]*inv; o1.w += acc[7]*inv;
    }

    float4* dst = (float4*)(out + eoff);
    __stcs(dst,     o0);          // out: never re-read, evict-first
    __stcs(dst + 1, o1);
}

extern "C" void kernel_launch(void* const* d_in, const int* in_sizes, int n_in,
                              void* d_out, int out_size) {
    const float* x    = (const float*)d_in[0];
    const float* A    = (const float*)d_in[1];
    const float* W    = (const float*)d_in[2];
    const float* b    = (const float*)d_in[3];
    const int*   root = (const int*)d_in[4];
    const int*   pn1  = (const int*)d_in[6];
    const int*   cn1  = (const int*)d_in[7];
    const int*   pn2  = (const int*)d_in[9];
    const int*   cn2  = (const int*)d_in[10];
    const int*   pe3  = (const int*)d_in[11];
    const int*   pn3  = (const int*)d_in[12];
    const int*   cn3  = (const int*)d_in[13];
    float* out = (float*)d_out;

    const int n1 = in_sizes[5];    // 600
    const int n3 = in_sizes[11];   // 5400
    const int n_roots = n1 / BR;   // 200

    static cudaStream_t s_side = nullptr;
    static cudaEvent_t  ev_fork = nullptr, ev_join = nullptr;
    if (!s_side) {
        cudaStreamCreateWithFlags(&s_side, cudaStreamNonBlocking);
        cudaEventCreateWithFlags(&ev_fork, cudaEventDisableTiming);
        cudaEventCreateWithFlags(&ev_join, cudaEventDisableTiming);
    }

    // prep + scale resolve only feed gather; run them concurrently with tree_kernel.
    cudaEventRecord(ev_fork, 0);
    cudaStreamWaitEvent(s_side, ev_fork, 0);
    prep_kernel<<<1, 1024, 0, s_side>>>(cn3, n3);
    const int padmax = n3 + 3 * NN;
    scale_fill_kernel<<<(padmax * 16 + 255) / 256, 256, 0, s_side>>>(A, pe3, pn3, cn3);
    cudaEventRecord(ev_join, s_side);

    tree_kernel<<<8 * n_roots, 256>>>(x, A, W, b, root, pn1, cn1, pn2, cn2);

    cudaStreamWaitEvent(0, ev_join, 0);
    gather_kernel<<<8 * NN, 128>>>(x, out);
}